// round 11
// baseline (speedup 1.0000x reference)
#include <cuda_runtime.h>
#include <cuda_fp16.h>
#include <cstdint>

// Problem constants
#define BB 64
#define SS 2048
#define HH 512
#define KK 512

// Scratch (static __device__ — no allocation)
__device__ float  g_c[BB * KK];            // e_fin + bias
__device__ float  g_scores[BB * SS];       // scores, then softmax weights
__device__ float  g_part[BB * 16 * HH];    // context partial sums
__device__ __half g_ench[(size_t)BB * SS * HH];   // enc in fp16 (written by scores)
__device__ __half g_wh[KK * HH];                  // w_enc in fp16

// ---------------------------------------------------------------------------
// helpers
// ---------------------------------------------------------------------------
__device__ __forceinline__ float tanha(float x) {
    float y;
    asm("tanh.approx.f32 %0, %1;" : "=f"(y) : "f"(x));
    return y;
}
__device__ __forceinline__ void cp16(uint32_t dst, const void* src) {
    asm volatile("cp.async.cg.shared.global [%0], [%1], 16;" :: "r"(dst), "l"(src));
}
__device__ __forceinline__ void cp_commit() {
    asm volatile("cp.async.commit_group;");
}
__device__ __forceinline__ void ldsm4(uint32_t (&r)[4], uint32_t addr) {
    asm volatile("ldmatrix.sync.aligned.m8n8.x4.shared.b16 {%0,%1,%2,%3}, [%4];"
                 : "=r"(r[0]), "=r"(r[1]), "=r"(r[2]), "=r"(r[3]) : "r"(addr));
}
__device__ __forceinline__ void mma_f16(float (&d)[4], const uint32_t (&a)[4],
                                        uint32_t b0, uint32_t b1) {
    asm volatile(
        "mma.sync.aligned.m16n8k16.row.col.f32.f16.f16.f32 "
        "{%0,%1,%2,%3},{%4,%5,%6,%7},{%8,%9},{%0,%1,%2,%3};"
        : "+f"(d[0]), "+f"(d[1]), "+f"(d[2]), "+f"(d[3])
        : "r"(a[0]), "r"(a[1]), "r"(a[2]), "r"(a[3]), "r"(b0), "r"(b1));
}
__device__ __forceinline__ uint32_t h2u(__half2 h) {
    return *reinterpret_cast<uint32_t*>(&h);
}

// ---------------------------------------------------------------------------
// conv_w: w_enc fp32 -> fp16
// ---------------------------------------------------------------------------
__global__ void conv_w_kernel(const float* __restrict__ attn_w) {
    int k = blockIdx.x, t = threadIdx.x;
    float2 v = *(const float2*)(attn_w + (size_t)k * (2 * HH) + 2 * t);
    ((__half2*)g_wh)[k * (HH / 2) + t] = __floats2half2_rn(v.x, v.y);
}

// ---------------------------------------------------------------------------
// Kernel A: c[b,k] = dot(fin[b,:], attn_w[k, 512:1024]) + attn_b[k]  (fp32)
// ---------------------------------------------------------------------------
__global__ void cvec_kernel(const float* __restrict__ fin,
                            const float* __restrict__ attn_w,
                            const float* __restrict__ attn_b) {
    __shared__ float fsm[HH];
    int b = blockIdx.x;
    int t = threadIdx.x;
    fsm[t] = fin[b * HH + t];
    fsm[t + 256] = fin[b * HH + t + 256];
    __syncthreads();

    int warp = t >> 5, lane = t & 31;
    for (int k = warp; k < KK; k += 8) {
        const float* wp = attn_w + (size_t)k * (2 * HH) + HH;
        float s = 0.f;
        #pragma unroll 4
        for (int h = lane; h < HH; h += 32) s += fsm[h] * wp[h];
        #pragma unroll
        for (int o = 16; o > 0; o >>= 1) s += __shfl_xor_sync(0xffffffffu, s, o);
        if (lane == 0) g_c[b * KK + k] = s + attn_b[k];
    }
}

// ---------------------------------------------------------------------------
// Kernel B: fused scores = sum_k v[k]*tanh(enc @ w_enc^T + c), fp16 mma.
// grid(32, 64): 64-s tile (x), batch (y). 256 thr = 8 warps (2 warp_m x 4
// warp_n), warp tile 32m x 64k. Block n-tile 256, 2 kc passes, 32h chunks.
// TWO CTAs PER SM (103 KB smem each): stalls in one CTA are covered by the
// other CTA's HMMAs. A (fp32 enc) converted/STS'd slice-by-slice under the
// mainloop; fp16 copy STG'd to g_ench. B double-buffered cp.async, 64B rows.
//
// SMEM (bytes): cs[512]f32 @0, vs[512]f32 @2048, ssum[4][64]f32 @4096,
//               A @5120 (64 rows x 1024B, XOR (row&7)<<4),
//               B @70656 (2 bufs x 256 rows x 64B, XOR ((row>>1)&3)<<4)
// total 103424 -> 2 CTAs/SM
// ---------------------------------------------------------------------------
#define SM_CS   0
#define SM_VS   2048
#define SM_SSUM 4096
#define SM_A    5120
#define SM_B    70656
#define BBUF    16384
#define SMEM_BYTES 103424

extern __shared__ uint32_t sdyn[];

__global__ __launch_bounds__(256, 2) void scores_fp16(
    const float* __restrict__ enc, const float* __restrict__ vw) {
    const int b = blockIdx.y;
    const int s0 = blockIdx.x * 64;
    const int tid = threadIdx.x;
    const int warp = tid >> 5, lane = tid & 31;
    const int g = lane >> 2, tg = lane & 3;
    const int warp_m = warp >> 2;      // 0..1  -> 32-row slices
    const int warp_n = warp & 3;       // 0..3  -> 64-k slices
    const uint32_t sbase = (uint32_t)__cvta_generic_to_shared(sdyn);

    float* cs = (float*)((char*)sdyn + SM_CS);
    float* vs = (float*)((char*)sdyn + SM_VS);
    float* ssum = (float*)((char*)sdyn + SM_SSUM);

    cs[tid] = g_c[b * KK + tid];
    cs[tid + 256] = g_c[b * KK + tid + 256];
    vs[tid] = vw[tid];
    vs[tid + 256] = vw[tid + 256];
    ssum[tid] = 0.f;

    // ---- B chunk loader: kc=(c>>4)*256, h0=(c&15)*32 halves; 64B rows ----
    auto loadB = [&](int c) {
        const uint32_t bb = sbase + SM_B + (c & 1) * BBUF;
        const int kc = (c >> 4) << 8;
        const int h0 = (c & 15) << 5;
        #pragma unroll
        for (int i = 0; i < 4; i++) {
            int idx = tid + i * 256;            // 0..1023
            int row = idx >> 2, u = idx & 3;
            uint32_t dst = bb + row * 64 + ((u * 16) ^ (((row >> 1) & 3) << 4));
            cp16(dst, g_wh + (size_t)(kc + row) * HH + h0 + u * 8);
        }
        cp_commit();
    };
    loadB(0);

    // ---- A slice pipeline: slice j covers h halves [j*32, j*32+32) ----
    // thread t owns row = t>>2 (0..63), unit u = t&3 (16B fp16 = 8 halves).
    const float* asrc = enc + ((size_t)b * SS + s0) * HH;
    __half* edst = g_ench + ((size_t)b * SS + s0) * HH;
    const int ar = tid >> 2, au = tid & 3;
    float4 ax, ay;

    auto ldgA = [&](int j) {
        const float* p = asrc + (size_t)ar * HH + j * 32 + au * 8;
        ax = ((const float4*)p)[0];
        ay = ((const float4*)p)[1];
    };
    auto stsA = [&](int j) {
        uint32_t w0 = h2u(__floats2half2_rn(ax.x, ax.y));
        uint32_t w1 = h2u(__floats2half2_rn(ax.z, ax.w));
        uint32_t w2 = h2u(__floats2half2_rn(ay.x, ay.y));
        uint32_t w3 = h2u(__floats2half2_rn(ay.z, ay.w));
        uint32_t col = (uint32_t)(j * 64 + au * 16);
        uint32_t d0 = sbase + SM_A + ar * 1024 + (col ^ ((ar & 7) << 4));
        asm volatile("st.shared.v4.b32 [%0], {%1,%2,%3,%4};"
                     :: "r"(d0), "r"(w0), "r"(w1), "r"(w2), "r"(w3));
        *(uint4*)(edst + (size_t)ar * HH + j * 32 + au * 8) =
            make_uint4(w0, w1, w2, w3);
    };
    ldgA(0);

    // ---- lane-constant ldmatrix addressing ----
    const int arow = warp_m * 32 + (lane & 7) + ((lane >> 3) & 1) * 8;   // +mi*16
    const int brow = warp_n * 64 + (lane & 7) + ((lane >> 3) & 1) * 8;   // +nip*16
    const int lcol16 = ((lane >> 4) & 1) * 16;    // +16B for k+8 halves
    const uint32_t a_lane = sbase + SM_A + arow * 1024;
    const uint32_t xor_a = (arow & 7) << 4;
    const uint32_t xor_b = ((brow >> 1) & 3) << 4;

    float acc[2][8][4];
    #pragma unroll
    for (int mi = 0; mi < 2; mi++)
        #pragma unroll
        for (int ni = 0; ni < 8; ni++)
            #pragma unroll
            for (int q = 0; q < 4; q++) acc[mi][ni][q] = 0.f;

    #pragma unroll 1
    for (int c = 0; c < 32; c++) {
        if (c < 16) stsA(c);        // slice c -> smem (visible after barrier)
        if (c < 31) {
            loadB(c + 1);
            asm volatile("cp.async.wait_group 1;");
        } else {
            asm volatile("cp.async.wait_group 0;");
        }
        __syncthreads();
        if (c < 15) ldgA(c + 1);    // hidden under this chunk's mma

        const uint32_t bb = sbase + SM_B + (c & 1) * BBUF + brow * 64;
        const int hbase = (c & 15) * 64;   // byte offset of chunk within A row

        #pragma unroll
        for (int kk = 0; kk < 2; kk++) {
            const uint32_t hoff = (uint32_t)(hbase + kk * 32 + lcol16);
            uint32_t a[2][4];
            #pragma unroll
            for (int mi = 0; mi < 2; mi++)
                ldsm4(a[mi], a_lane + mi * 16384 + (hoff ^ xor_a));
            #pragma unroll
            for (int nip = 0; nip < 4; nip++) {
                uint32_t r[4];
                ldsm4(r, bb + nip * 1024 +
                          (((uint32_t)(kk * 32 + lcol16)) ^ xor_b));
                #pragma unroll
                for (int mi = 0; mi < 2; mi++) {
                    mma_f16(acc[mi][2 * nip], a[mi], r[0], r[2]);
                    mma_f16(acc[mi][2 * nip + 1], a[mi], r[1], r[3]);
                }
            }
        }

        if ((c & 15) == 15) {
            // epilogue for this kc: tanh(acc + c)*v, reduce 64 k per warp
            const int kc = (c >> 4) << 8;
            float rs[4];
            #pragma unroll
            for (int i = 0; i < 4; i++) rs[i] = 0.f;
            #pragma unroll
            for (int ni = 0; ni < 8; ni++) {
                int kg = kc + warp_n * 64 + ni * 8 + tg * 2;
                float c0 = cs[kg], c1 = cs[kg + 1];
                float v0 = vs[kg], v1 = vs[kg + 1];
                #pragma unroll
                for (int mi = 0; mi < 2; mi++) {
                    rs[mi * 2 + 0] += tanha(acc[mi][ni][0] + c0) * v0
                                    + tanha(acc[mi][ni][1] + c1) * v1;
                    rs[mi * 2 + 1] += tanha(acc[mi][ni][2] + c0) * v0
                                    + tanha(acc[mi][ni][3] + c1) * v1;
                    acc[mi][ni][0] = 0.f; acc[mi][ni][1] = 0.f;
                    acc[mi][ni][2] = 0.f; acc[mi][ni][3] = 0.f;
                }
            }
            #pragma unroll
            for (int i = 0; i < 4; i++) {
                rs[i] += __shfl_xor_sync(0xffffffffu, rs[i], 1);
                rs[i] += __shfl_xor_sync(0xffffffffu, rs[i], 2);
            }
            if (tg == 0) {
                #pragma unroll
                for (int mi = 0; mi < 2; mi++) {
                    int row = warp_m * 32 + mi * 16 + g;
                    ssum[warp_n * 64 + row]     += rs[mi * 2 + 0];
                    ssum[warp_n * 64 + row + 8] += rs[mi * 2 + 1];
                }
            }
        }
        __syncthreads();
    }

    if (tid < 64) {
        g_scores[b * SS + s0 + tid] =
            (ssum[tid] + ssum[64 + tid]) + (ssum[128 + tid] + ssum[192 + tid]);
    }
}

// ---------------------------------------------------------------------------
// Kernel C: softmax over s (2048) per batch; in-place on g_scores
// ---------------------------------------------------------------------------
__global__ void softmax_kernel() {
    __shared__ float red[256];
    int b = blockIdx.x, t = threadIdx.x;
    float v[8];
    float m = -1e30f;
    #pragma unroll
    for (int i = 0; i < 8; i++) {
        v[i] = g_scores[b * SS + i * 256 + t];
        m = fmaxf(m, v[i]);
    }
    red[t] = m;
    __syncthreads();
    for (int o = 128; o > 0; o >>= 1) {
        if (t < o) red[t] = fmaxf(red[t], red[t + o]);
        __syncthreads();
    }
    float mx = red[0];
    __syncthreads();
    float s = 0.f;
    #pragma unroll
    for (int i = 0; i < 8; i++) {
        v[i] = __expf(v[i] - mx);
        s += v[i];
    }
    red[t] = s;
    __syncthreads();
    for (int o = 128; o > 0; o >>= 1) {
        if (t < o) red[t] += red[t + o];
        __syncthreads();
    }
    float inv = 1.f / red[0];
    #pragma unroll
    for (int i = 0; i < 8; i++)
        g_scores[b * SS + i * 256 + t] = v[i] * inv;
}

// ---------------------------------------------------------------------------
// Kernel D: context partials over 128-s chunks, fp16 enc (from scores STG)
// grid(16, 64), block(128); thread t owns h = 4t..4t+3
// ---------------------------------------------------------------------------
__global__ void context_kernel() {
    __shared__ float ws[128];
    int b = blockIdx.y, sc = blockIdx.x;
    int t = threadIdx.x;
    ws[t] = g_scores[b * SS + sc * 128 + t];
    __syncthreads();
    const __half* ep = g_ench + ((size_t)b * SS + sc * 128) * HH + 4 * t;
    float ax = 0.f, ay = 0.f, az = 0.f, aw = 0.f;
    #pragma unroll 4
    for (int j = 0; j < 128; j++) {
        float w = ws[j];
        uint2 u = *(const uint2*)(ep + (size_t)j * HH);
        float2 f0 = __half22float2(*reinterpret_cast<const __half2*>(&u.x));
        float2 f1 = __half22float2(*reinterpret_cast<const __half2*>(&u.y));
        ax += w * f0.x; ay += w * f0.y; az += w * f1.x; aw += w * f1.y;
    }
    float4 r; r.x = ax; r.y = ay; r.z = az; r.w = aw;
    ((float4*)(g_part + ((size_t)(b * 16 + sc)) * HH))[t] = r;
}

// ---------------------------------------------------------------------------
// Kernel E: reduce 16 partials -> context
// ---------------------------------------------------------------------------
__global__ void reduce_ctx(float* __restrict__ out) {
    int b = blockIdx.x, h = threadIdx.x;
    float s = 0.f;
    #pragma unroll
    for (int i = 0; i < 16; i++) s += g_part[((size_t)(b * 16 + i)) * HH + h];
    out[b * HH + h] = s;
}

// ---------------------------------------------------------------------------
extern "C" void kernel_launch(void* const* d_in, const int* in_sizes, int n_in,
                              void* d_out, int out_size) {
    const float* enc    = (const float*)d_in[0];   // (64, 2048, 512)
    const float* fin    = (const float*)d_in[1];   // (64, 512)
    const float* attn_w = (const float*)d_in[2];   // (512, 1024)
    const float* attn_b = (const float*)d_in[3];   // (512,)
    const float* v_w    = (const float*)d_in[4];   // (1, 512)
    float* out = (float*)d_out;                    // (64, 512)

    cudaFuncSetAttribute(scores_fp16,
                         cudaFuncAttributeMaxDynamicSharedMemorySize, SMEM_BYTES);

    conv_w_kernel<<<KK, 256>>>(attn_w);
    cvec_kernel<<<BB, 256>>>(fin, attn_w, attn_b);
    scores_fp16<<<dim3(SS / 64, BB), 256, SMEM_BYTES>>>(enc, v_w);
    softmax_kernel<<<BB, 256>>>();
    context_kernel<<<dim3(16, BB), 128>>>();
    reduce_ctx<<<BB, 512>>>(out);
}